// round 15
// baseline (speedup 1.0000x reference)
#include <cuda_runtime.h>
#include <cuda_bf16.h>
#include <math.h>
#include <stdint.h>

#define D_MODEL 1024
#define HEADS 16
#define HEAD_DIM 64
#define BATCH 4
#define SEQ 2048
#define MTOT (BATCH * SEQ) /* 8192 */
#define WSZ (D_MODEL * D_MODEL)
#define PL ((size_t)MTOT * D_MODEL)

typedef __nv_bfloat16 bf16;

// ---- scratch (static __device__; allocation APIs forbidden) ----
__device__ bf16 g_xh[(size_t)MTOT * D_MODEL];
__device__ bf16 g_xl[(size_t)MTOT * D_MODEL];
__device__ bf16 g_qkvh[(size_t)3 * MTOT * D_MODEL];
__device__ bf16 g_qkvl[(size_t)3 * MTOT * D_MODEL];
__device__ bf16 g_mh[(size_t)MTOT * D_MODEL];
__device__ bf16 g_ml[(size_t)MTOT * D_MODEL];
__device__ bf16 g_wh[(size_t)4 * WSZ];
__device__ bf16 g_wl[(size_t)4 * WSZ];

// ============================ PTX helpers ============================
__device__ __forceinline__ uint32_t smem_u32(const void* p) {
    uint32_t a;
    asm("{ .reg .u64 t; cvta.to.shared.u64 t, %1; cvt.u32.u64 %0, t; }"
        : "=r"(a) : "l"(p));
    return a;
}
__device__ __forceinline__ void cp16(uint32_t s, const void* g) {
    asm volatile("cp.async.cg.shared.global [%0], [%1], 16;" :: "r"(s), "l"(g) : "memory");
}
__device__ __forceinline__ void cp_commit() {
    asm volatile("cp.async.commit_group;" ::: "memory");
}
template <int N> __device__ __forceinline__ void cp_wait() {
    asm volatile("cp.async.wait_group %0;" :: "n"(N) : "memory");
}
__device__ __forceinline__ void ldsm4(uint32_t* r, uint32_t addr) {
    asm volatile("ldmatrix.sync.aligned.m8n8.x4.shared.b16 {%0,%1,%2,%3}, [%4];"
                 : "=r"(r[0]), "=r"(r[1]), "=r"(r[2]), "=r"(r[3]) : "r"(addr));
}
__device__ __forceinline__ void ldsm4t(uint32_t* r, uint32_t addr) {
    asm volatile("ldmatrix.sync.aligned.m8n8.x4.trans.shared.b16 {%0,%1,%2,%3}, [%4];"
                 : "=r"(r[0]), "=r"(r[1]), "=r"(r[2]), "=r"(r[3]) : "r"(addr));
}
__device__ __forceinline__ void mma16816(float* c, const uint32_t* a,
                                         uint32_t b0, uint32_t b1) {
    asm volatile(
        "mma.sync.aligned.m16n8k16.row.col.f32.bf16.bf16.f32 "
        "{%0,%1,%2,%3},{%4,%5,%6,%7},{%8,%9},{%0,%1,%2,%3};"
        : "+f"(c[0]), "+f"(c[1]), "+f"(c[2]), "+f"(c[3])
        : "r"(a[0]), "r"(a[1]), "r"(a[2]), "r"(a[3]), "r"(b0), "r"(b1));
}
__device__ __forceinline__ uint32_t sw128(uint32_t o) { return o ^ ((o >> 3) & 0x70); }
__device__ __forceinline__ uint32_t sw64(uint32_t o)  { return o ^ ((o >> 3) & 0x30); }

// Split a float pair into packed bf16x2 hi + packed bf16x2 lo (6 ops total).
__device__ __forceinline__ uint32_t pack_split(float v0, float v1, uint32_t& lp) {
    uint32_t hp;
    asm("cvt.rn.bf16x2.f32 %0, %1, %2;" : "=r"(hp) : "f"(v1), "f"(v0));
    float h0 = __uint_as_float(hp << 16);
    float h1 = __uint_as_float(hp & 0xffff0000u);
    float l0 = v0 - h0, l1 = v1 - h1;
    asm("cvt.rn.bf16x2.f32 %0, %1, %2;" : "=r"(lp) : "f"(l1), "f"(l0));
    return hp;
}
// Hi-only packed convert (1 op).
__device__ __forceinline__ uint32_t pack_hi(float v0, float v1) {
    uint32_t hp;
    asm("cvt.rn.bf16x2.f32 %0, %1, %2;" : "=r"(hp) : "f"(v1), "f"(v0));
    return hp;
}

#define LOG2E 1.4426950408889634f
#define SKIP_MARGIN 25.0f

// ============================ mma.sync GEMM v3 (unchanged) ============================
#define GBK 32
#define GNCHUNK (D_MODEL / GBK) /* 32 */
#define GARR 8192
#define GST (4 * GARR)
#define GEMM_SMEM (3 * GST)     /* 98304 */

__global__ __launch_bounds__(256, 2) void gemm_mma(
    const bf16* __restrict__ Ah, const bf16* __restrict__ Al,
    const bf16* __restrict__ BhAll, const bf16* __restrict__ BlAll,
    float* __restrict__ Cf, bf16* __restrict__ ChAll, bf16* __restrict__ ClAll,
    float scale0)
{
    extern __shared__ char smem[];
    const uint32_t sb = smem_u32(smem);
    const int tid = threadIdx.x;
    const int wid = tid >> 5, lane = tid & 31;
    const int wm = wid & 3, wn = wid >> 2;
    const int rowBase = blockIdx.y * 128;
    const int colBase = blockIdx.x * 128;

    const bf16* Bh = BhAll + (size_t)blockIdx.z * WSZ;
    const bf16* Bl = BlAll + (size_t)blockIdx.z * WSZ;

    const bf16* srcAh = Ah + (size_t)rowBase * D_MODEL;
    const bf16* srcAl = Al + (size_t)rowBase * D_MODEL;
    const bf16* srcBh = Bh + (size_t)colBase * D_MODEL;
    const bf16* srcBl = Bl + (size_t)colBase * D_MODEL;

    float acc[2][8][4];
#pragma unroll
    for (int mi = 0; mi < 2; mi++)
#pragma unroll
        for (int ni = 0; ni < 8; ni++)
#pragma unroll
            for (int j = 0; j < 4; j++) acc[mi][ni][j] = 0.f;

    auto load_chunk = [&](int c, int stg) {
        const uint32_t tb = sb + stg * GST;
        const int kofs = c * GBK;
#pragma unroll
        for (int i = 0; i < 2; i++) {
            int f = i * 256 + tid;
            int row = f >> 2, cc = f & 3;
            uint32_t so = sw64((uint32_t)(row * 64 + cc * 16));
            const size_t go = (size_t)row * D_MODEL + kofs + cc * 8;
            cp16(tb + so, srcAh + go);
            cp16(tb + GARR + so, srcAl + go);
            cp16(tb + 2 * GARR + so, srcBh + go);
            cp16(tb + 3 * GARR + so, srcBl + go);
        }
    };

    const uint32_t lrow = lane & 15, lcol = lane >> 4;

    load_chunk(0, 0); cp_commit();
    load_chunk(1, 1); cp_commit();

    for (int c = 0; c < GNCHUNK; c++) {
        if (c + 1 < GNCHUNK) cp_wait<1>(); else cp_wait<0>();
        __syncthreads();
        if (c + 2 < GNCHUNK) { load_chunk(c + 2, (c + 2) % 3); cp_commit(); }

        const uint32_t tb = sb + (c % 3) * GST;
#pragma unroll
        for (int k16 = 0; k16 < 2; k16++) {
            const uint32_t kb = k16 * 32;
            uint32_t a_h[2][4], a_l[2][4], bfr[4][4];
#pragma unroll
            for (int mi = 0; mi < 2; mi++) {
                uint32_t o = (uint32_t)((wm * 32 + mi * 16 + lrow) * 64 + kb + lcol * 16);
                ldsm4(a_h[mi], tb + sw64(o));
                ldsm4(a_l[mi], tb + GARR + sw64(o));
            }
#pragma unroll
            for (int nb = 0; nb < 4; nb++) {
                uint32_t o = (uint32_t)((wn * 64 + nb * 16 + lrow) * 64 + kb + lcol * 16);
                ldsm4(bfr[nb], tb + 2 * GARR + sw64(o));
            }
#pragma unroll
            for (int nb = 0; nb < 4; nb++)
#pragma unroll
                for (int mi = 0; mi < 2; mi++) {
                    mma16816(acc[mi][2 * nb], a_h[mi], bfr[nb][0], bfr[nb][2]);
                    mma16816(acc[mi][2 * nb + 1], a_h[mi], bfr[nb][1], bfr[nb][3]);
                }
#pragma unroll
            for (int nb = 0; nb < 4; nb++)
#pragma unroll
                for (int mi = 0; mi < 2; mi++) {
                    mma16816(acc[mi][2 * nb], a_l[mi], bfr[nb][0], bfr[nb][2]);
                    mma16816(acc[mi][2 * nb + 1], a_l[mi], bfr[nb][1], bfr[nb][3]);
                }
#pragma unroll
            for (int nb = 0; nb < 4; nb++) {
                uint32_t o = (uint32_t)((wn * 64 + nb * 16 + lrow) * 64 + kb + lcol * 16);
                ldsm4(bfr[nb], tb + 3 * GARR + sw64(o));
            }
#pragma unroll
            for (int nb = 0; nb < 4; nb++)
#pragma unroll
                for (int mi = 0; mi < 2; mi++) {
                    mma16816(acc[mi][2 * nb], a_h[mi], bfr[nb][0], bfr[nb][2]);
                    mma16816(acc[mi][2 * nb + 1], a_h[mi], bfr[nb][1], bfr[nb][3]);
                }
        }
    }

    __syncthreads();

    const int g = lane >> 2, t4 = lane & 3;
    if (ChAll) {
        bf16* Ch = ChAll + (size_t)blockIdx.z * MTOT * D_MODEL;
        bf16* Cl = ClAll + (size_t)blockIdx.z * MTOT * D_MODEL;
        const float sc = (blockIdx.z == 0) ? scale0 : 1.0f;
#pragma unroll
        for (int mi = 0; mi < 2; mi++)
#pragma unroll
            for (int ni = 0; ni < 8; ni++) {
                int r = rowBase + wm * 32 + mi * 16 + g;
                int col = colBase + wn * 64 + ni * 8 + t4 * 2;
#pragma unroll
                for (int half = 0; half < 2; half++) {
                    uint32_t lp;
                    uint32_t hp = pack_split(acc[mi][ni][2 * half] * sc,
                                             acc[mi][ni][2 * half + 1] * sc, lp);
                    size_t o = (size_t)(r + 8 * half) * D_MODEL + col;
                    *(uint32_t*)&Ch[o] = hp;
                    *(uint32_t*)&Cl[o] = lp;
                }
            }
    } else {
#pragma unroll
        for (int mi = 0; mi < 2; mi++)
#pragma unroll
            for (int ni = 0; ni < 8; ni++) {
                int r = rowBase + wm * 32 + mi * 16 + g;
                int col = colBase + wn * 64 + ni * 8 + t4 * 2;
                *(float2*)&Cf[(size_t)r * D_MODEL + col] =
                    make_float2(acc[mi][ni][0], acc[mi][ni][1]);
                *(float2*)&Cf[(size_t)(r + 8) * D_MODEL + col] =
                    make_float2(acc[mi][ni][2], acc[mi][ni][3]);
            }
    }
}

// ==================== conversion kernels (unchanged) ====================
__global__ __launch_bounds__(256) void split_kernel(
    const float* __restrict__ in, bf16* __restrict__ hi, bf16* __restrict__ lo, int n2)
{
    int i = blockIdx.x * blockDim.x + threadIdx.x;
    if (i >= n2) return;
    float2 v = ((const float2*)in)[i];
    uint32_t lp;
    uint32_t hp = pack_split(v.x, v.y, lp);
    ((uint32_t*)hi)[i] = hp;
    ((uint32_t*)lo)[i] = lp;
}

__global__ __launch_bounds__(256) void wT_split4(
    const float* __restrict__ W0, const float* __restrict__ W1,
    const float* __restrict__ W2, const float* __restrict__ W3,
    bf16* __restrict__ Th, bf16* __restrict__ Tl)
{
    const float* W = (blockIdx.z == 0) ? W0 : (blockIdx.z == 1) ? W1
                     : (blockIdx.z == 2) ? W2 : W3;
    Th += (size_t)blockIdx.z * WSZ;
    Tl += (size_t)blockIdx.z * WSZ;
    __shared__ float t[32][33];
    int nx = blockIdx.x * 32 + threadIdx.x;
#pragma unroll
    for (int j = 0; j < 32; j += 8)
        t[threadIdx.y + j][threadIdx.x] =
            W[(size_t)(blockIdx.y * 32 + threadIdx.y + j) * D_MODEL + nx];
    __syncthreads();
    int k = blockIdx.y * 32 + threadIdx.x;
#pragma unroll
    for (int j = 0; j < 32; j += 8) {
        int n = blockIdx.x * 32 + threadIdx.y + j;
        float v = t[threadIdx.x][threadIdx.y + j];
        bf16 h = __float2bfloat16(v);
        bf16 l = __float2bfloat16(v - __bfloat162float(h));
        Th[(size_t)n * D_MODEL + k] = h;
        Tl[(size_t)n * D_MODEL + k] = l;
    }
}

// ==================== tensor-core flash attention v10 ====================
// v9 + negligible-tile skipping: a row-group whose tile max is > SKIP_MARGIN
// below the running max contributes < 2^-36 per weight; skip its exp/rescale/
// PV entirely (warp-uniform via __all_sync). QK always computed (needed for
// the max). Error bound ~1e-9, invisible at rel_err 3e-4.
#define KROW 128
#define AKT 8192                       /* one 64x128B array */
#define ASTG (4 * AKT)                 /* Kh,Kl,Vh,Vl = 32KB per stage */
#define AQL (2 * AKT)                  /* Ql: 128x128B = 16KB */
#define ATTN_SMEM (2 * ASTG + AQL)     /* 81920 */

__global__ __launch_bounds__(128, 2) void attn_mma(
    const bf16* __restrict__ qkvh, const bf16* __restrict__ qkvl,
    bf16* __restrict__ MH, bf16* __restrict__ ML)
{
    extern __shared__ char smraw[];
    const uint32_t sb = smem_u32(smraw);
    const int tid = threadIdx.x;
    const int wid = tid >> 5, lane = tid & 31;
    const uint32_t lrow = lane & 15, lcol = lane >> 4;
    const int g = lane >> 2, t4 = lane & 3;

    const int q0 = blockIdx.x * 128;
    const int b = blockIdx.z;
    const size_t qrow = (size_t)b * SEQ + q0;
    const size_t krow0 = (size_t)b * SEQ;
    const int hofs = blockIdx.y * HEAD_DIM;

    auto load_tile = [&](int t, int buf) {
        const size_t kr = krow0 + (size_t)t * 64;
        const uint32_t tb = sb + buf * ASTG;
#pragma unroll
        for (int i = 0; i < 16; i++) {
            int f = i * 128 + tid;          // 0..2047
            int arr = f >> 9;               // 0:Kh 1:Kl 2:Vh 3:Vl
            int r = (f >> 3) & 63, cg = f & 7;
            const bf16* p = ((arr & 1) ? qkvl : qkvh) + ((arr < 2) ? PL : 2 * PL);
            cp16(tb + arr * AKT + sw128((uint32_t)(r * KROW + cg * 16)),
                 p + (kr + r) * D_MODEL + hofs + cg * 8);
        }
    };

    // Ql tile (128 rows) -> smem, folded into commit group 0
#pragma unroll
    for (int i = 0; i < 8; i++) {
        int f = i * 128 + tid;              // 0..1023
        int r = f >> 3, cg = f & 7;
        cp16(sb + 2 * ASTG + sw128((uint32_t)(r * KROW + cg * 16)),
             qkvl + (qrow + r) * D_MODEL + hofs + cg * 8);
    }
    load_tile(0, 0); cp_commit();
    load_tile(1, 1); cp_commit();

    // Qh fragments direct from gmem, 2 row-groups
    uint32_t qhf[2][4][4];
#pragma unroll
    for (int rg = 0; rg < 2; rg++) {
        const size_t r0 = qrow + wid * 32 + rg * 16 + g;
        const int c0 = hofs + t4 * 2;
#pragma unroll
        for (int kc = 0; kc < 4; kc++)
#pragma unroll
            for (int q = 0; q < 4; q++) {
                size_t r = r0 + ((q & 1) ? 8 : 0);
                int c = c0 + kc * 16 + ((q & 2) ? 8 : 0);
                qhf[rg][kc][q] = *(const uint32_t*)&qkvh[r * D_MODEL + c];
            }
    }

    float o[2][8][4];
#pragma unroll
    for (int rg = 0; rg < 2; rg++)
#pragma unroll
        for (int di = 0; di < 8; di++)
#pragma unroll
            for (int j = 0; j < 4; j++) o[rg][di][j] = 0.f;
    float m_prev[2][2] = {{-1e30f, -1e30f}, {-1e30f, -1e30f}};
    float lsum[2][2] = {{0.f, 0.f}, {0.f, 0.f}};

    const int NT = SEQ / 64;  // 32
    for (int t = 0; t < NT; t++) {
        if (t + 2 < NT) cp_wait<1>(); else cp_wait<0>();
        __syncthreads();                    // tile t resident

        const uint32_t tb = sb + (t & 1) * ASTG;

        // ---- S = Q K^T (3-term), kf shared across both row-groups ----
        float s[2][8][4];
#pragma unroll
        for (int rg = 0; rg < 2; rg++)
#pragma unroll
            for (int ni = 0; ni < 8; ni++)
#pragma unroll
                for (int j = 0; j < 4; j++) s[rg][ni][j] = 0.f;

#pragma unroll
        for (int kc = 0; kc < 4; kc++) {
            uint32_t kf[4][4];
#pragma unroll
            for (int np = 0; np < 4; np++)
                ldsm4(kf[np], tb + sw128((uint32_t)((np * 16 + lrow) * KROW +
                                                    kc * 32 + lcol * 16)));
#pragma unroll
            for (int rg = 0; rg < 2; rg++)
#pragma unroll
                for (int ni = 0; ni < 8; ni++) {
                    int np = ni >> 1, hl = ni & 1;
                    mma16816(s[rg][ni], qhf[rg][kc], kf[np][hl], kf[np][hl + 2]);
                }
#pragma unroll
            for (int rg = 0; rg < 2; rg++) {
                uint32_t qlf[4];
                ldsm4(qlf, sb + 2 * ASTG +
                      sw128((uint32_t)((wid * 32 + rg * 16 + lrow) * KROW +
                                       kc * 32 + lcol * 16)));
#pragma unroll
                for (int ni = 0; ni < 8; ni++) {
                    int np = ni >> 1, hl = ni & 1;
                    mma16816(s[rg][ni], qlf, kf[np][hl], kf[np][hl + 2]);
                }
            }
        }
#pragma unroll
        for (int kc = 0; kc < 4; kc++) {
            uint32_t kf[4][4];
#pragma unroll
            for (int np = 0; np < 4; np++)
                ldsm4(kf[np], tb + AKT + sw128((uint32_t)((np * 16 + lrow) * KROW +
                                                          kc * 32 + lcol * 16)));
#pragma unroll
            for (int rg = 0; rg < 2; rg++)
#pragma unroll
                for (int ni = 0; ni < 8; ni++) {
                    int np = ni >> 1, hl = ni & 1;
                    mma16816(s[rg][ni], qhf[rg][kc], kf[np][hl], kf[np][hl + 2]);
                }
        }

        // ---- online softmax with negligible-tile skip ----
        bool doit[2];
#pragma unroll
        for (int rg = 0; rg < 2; rg++) {
            float mx[2];
#pragma unroll
            for (int sub = 0; sub < 2; sub++) {
                float m = -1e30f;
#pragma unroll
                for (int ni = 0; ni < 8; ni++)
                    m = fmaxf(m, fmaxf(s[rg][ni][2 * sub], s[rg][ni][2 * sub + 1]));
                m = fmaxf(m, __shfl_xor_sync(0xffffffffu, m, 1));
                m = fmaxf(m, __shfl_xor_sync(0xffffffffu, m, 2));
                mx[sub] = m;
            }
            bool negligible = (mx[0] < m_prev[rg][0] - SKIP_MARGIN) &&
                              (mx[1] < m_prev[rg][1] - SKIP_MARGIN);
            doit[rg] = !__all_sync(0xffffffffu, negligible);
            if (doit[rg]) {
#pragma unroll
                for (int sub = 0; sub < 2; sub++) {
                    float mn = fmaxf(m_prev[rg][sub], mx[sub]);
                    float mn2 = mn * LOG2E;
                    float al = exp2f(fmaf(m_prev[rg][sub], LOG2E, -mn2));
                    float sum = 0.f;
#pragma unroll
                    for (int ni = 0; ni < 8; ni++) {
                        float p0 = exp2f(fmaf(s[rg][ni][2 * sub], LOG2E, -mn2));
                        float p1 = exp2f(fmaf(s[rg][ni][2 * sub + 1], LOG2E, -mn2));
                        s[rg][ni][2 * sub] = p0;
                        s[rg][ni][2 * sub + 1] = p1;
                        sum += p0 + p1;
                    }
                    sum += __shfl_xor_sync(0xffffffffu, sum, 1);
                    sum += __shfl_xor_sync(0xffffffffu, sum, 2);
                    lsum[rg][sub] = lsum[rg][sub] * al + sum;
                    m_prev[rg][sub] = mn;
#pragma unroll
                    for (int di = 0; di < 8; di++) {
                        o[rg][di][2 * sub] *= al;
                        o[rg][di][2 * sub + 1] *= al;
                    }
                }
            }
        }

        // ---- O += P V (2-term; skipped row-groups contribute nothing) ----
        if (doit[0] || doit[1]) {
#pragma unroll
            for (int kc2 = 0; kc2 < 4; kc2++) {
                int j0 = 2 * kc2, j1 = j0 + 1;
                uint32_t ah[2][4];
#pragma unroll
                for (int rg = 0; rg < 2; rg++)
                    if (doit[rg])
#pragma unroll
                        for (int q = 0; q < 4; q++) {
                            const float* sp = (q & 2) ? s[rg][j1] : s[rg][j0];
                            ah[rg][q] = pack_hi(sp[(q & 1) * 2], sp[(q & 1) * 2 + 1]);
                        }
#pragma unroll
                for (int dp = 0; dp < 4; dp++) {
                    uint32_t a = sw128((uint32_t)((kc2 * 16 + lrow) * KROW +
                                                  dp * 32 + lcol * 16));
                    uint32_t vh4[4], vl4[4];
                    ldsm4t(vh4, tb + 2 * AKT + a);
                    ldsm4t(vl4, tb + 3 * AKT + a);
#pragma unroll
                    for (int rg = 0; rg < 2; rg++)
                        if (doit[rg])
#pragma unroll
                            for (int dd = 0; dd < 2; dd++) {
                                int di = 2 * dp + dd, off = dd * 2;
                                mma16816(o[rg][di], ah[rg], vh4[off], vh4[off + 1]);
                                mma16816(o[rg][di], ah[rg], vl4[off], vl4[off + 1]);
                            }
                }
            }
        }

        __syncthreads();                    // all warps done with buffer t&1
        if (t + 2 < NT) { load_tile(t + 2, t & 1); cp_commit(); }
    }

    // ---- epilogue ----
#pragma unroll
    for (int rg = 0; rg < 2; rg++) {
        float inv_l[2] = {1.f / lsum[rg][0], 1.f / lsum[rg][1]};
#pragma unroll
        for (int di = 0; di < 8; di++) {
#pragma unroll
            for (int sub = 0; sub < 2; sub++) {
                uint32_t lp;
                uint32_t hp = pack_split(o[rg][di][2 * sub] * inv_l[sub],
                                         o[rg][di][2 * sub + 1] * inv_l[sub], lp);
                size_t idx = (qrow + wid * 32 + rg * 16 + g + 8 * sub) * D_MODEL +
                             hofs + di * 8 + t4 * 2;
                *(uint32_t*)&MH[idx] = hp;
                *(uint32_t*)&ML[idx] = lp;
            }
        }
    }
}

// ---------------------------------------------------------------------------
extern "C" void kernel_launch(void* const* d_in, const int* in_sizes, int n_in,
                              void* d_out, int out_size)
{
    (void)in_sizes; (void)n_in; (void)out_size;
    const float* x    = (const float*)d_in[0];
    const float* W_q  = (const float*)d_in[1];
    const float* W_k  = (const float*)d_in[2];
    const float* W_v  = (const float*)d_in[3];
    const float* fc_o = (const float*)d_in[4];
    float* out = (float*)d_out;

    bf16 *xh, *xl, *qkvh, *qkvl, *mh, *ml, *wh, *wl;
    cudaGetSymbolAddress((void**)&xh, g_xh);
    cudaGetSymbolAddress((void**)&xl, g_xl);
    cudaGetSymbolAddress((void**)&qkvh, g_qkvh);
    cudaGetSymbolAddress((void**)&qkvl, g_qkvl);
    cudaGetSymbolAddress((void**)&mh, g_mh);
    cudaGetSymbolAddress((void**)&ml, g_ml);
    cudaGetSymbolAddress((void**)&wh, g_wh);
    cudaGetSymbolAddress((void**)&wl, g_wl);

    cudaFuncSetAttribute(gemm_mma, cudaFuncAttributeMaxDynamicSharedMemorySize, GEMM_SMEM);
    cudaFuncSetAttribute(attn_mma, cudaFuncAttributeMaxDynamicSharedMemorySize, ATTN_SMEM);

    const int n2_x = MTOT * D_MODEL / 2;
    dim3 wgrid(D_MODEL / 32, D_MODEL / 32, 4);
    dim3 wblk(32, 8);

    split_kernel<<<(n2_x + 255) / 256, 256>>>(x, xh, xl, n2_x);
    wT_split4<<<wgrid, wblk>>>(W_q, W_k, W_v, fc_o, wh, wl);

    dim3 ggrid3(D_MODEL / 128, MTOT / 128, 3);
    gemm_mma<<<ggrid3, 256, GEMM_SMEM>>>(xh, xl, wh, wl, nullptr, qkvh, qkvl, 0.125f);

    dim3 attn_grid(SEQ / 128, HEADS, BATCH);   // (16, 16, 4) = 1024 CTAs
    attn_mma<<<attn_grid, 128, ATTN_SMEM>>>(qkvh, qkvl, mh, ml);

    dim3 ggrid1(D_MODEL / 128, MTOT / 128, 1);
    gemm_mma<<<ggrid1, 256, GEMM_SMEM>>>(mh, ml, wh + (size_t)3 * WSZ,
                                         wl + (size_t)3 * WSZ, out, nullptr, nullptr, 1.0f);
}

// round 16
// speedup vs baseline: 1.0414x; 1.0414x over previous
#include <cuda_runtime.h>
#include <cuda_bf16.h>
#include <math.h>
#include <stdint.h>

#define D_MODEL 1024
#define HEADS 16
#define HEAD_DIM 64
#define BATCH 4
#define SEQ 2048
#define MTOT (BATCH * SEQ) /* 8192 */
#define WSZ (D_MODEL * D_MODEL)
#define PL ((size_t)MTOT * D_MODEL)

typedef __nv_bfloat16 bf16;

// ---- scratch (static __device__; allocation APIs forbidden) ----
__device__ bf16 g_xh[(size_t)MTOT * D_MODEL];
__device__ bf16 g_xl[(size_t)MTOT * D_MODEL];
__device__ bf16 g_qkvh[(size_t)3 * MTOT * D_MODEL];
__device__ bf16 g_qkvl[(size_t)3 * MTOT * D_MODEL];
__device__ float g_m[(size_t)MTOT * D_MODEL];   // merged (fp32, tf32-rounded)
__device__ float g_wt[(size_t)WSZ];             // fc_o^T (fp32, tf32-rounded)
__device__ bf16 g_wh[(size_t)3 * WSZ];
__device__ bf16 g_wl[(size_t)3 * WSZ];

// ============================ PTX helpers ============================
__device__ __forceinline__ uint32_t smem_u32(const void* p) {
    uint32_t a;
    asm("{ .reg .u64 t; cvta.to.shared.u64 t, %1; cvt.u32.u64 %0, t; }"
        : "=r"(a) : "l"(p));
    return a;
}
__device__ __forceinline__ void cp16(uint32_t s, const void* g) {
    asm volatile("cp.async.cg.shared.global [%0], [%1], 16;" :: "r"(s), "l"(g) : "memory");
}
__device__ __forceinline__ void cp_commit() {
    asm volatile("cp.async.commit_group;" ::: "memory");
}
template <int N> __device__ __forceinline__ void cp_wait() {
    asm volatile("cp.async.wait_group %0;" :: "n"(N) : "memory");
}
__device__ __forceinline__ void ldsm4(uint32_t* r, uint32_t addr) {
    asm volatile("ldmatrix.sync.aligned.m8n8.x4.shared.b16 {%0,%1,%2,%3}, [%4];"
                 : "=r"(r[0]), "=r"(r[1]), "=r"(r[2]), "=r"(r[3]) : "r"(addr));
}
__device__ __forceinline__ void ldsm4t(uint32_t* r, uint32_t addr) {
    asm volatile("ldmatrix.sync.aligned.m8n8.x4.trans.shared.b16 {%0,%1,%2,%3}, [%4];"
                 : "=r"(r[0]), "=r"(r[1]), "=r"(r[2]), "=r"(r[3]) : "r"(addr));
}
__device__ __forceinline__ void mma16816(float* c, const uint32_t* a,
                                         uint32_t b0, uint32_t b1) {
    asm volatile(
        "mma.sync.aligned.m16n8k16.row.col.f32.bf16.bf16.f32 "
        "{%0,%1,%2,%3},{%4,%5,%6,%7},{%8,%9},{%0,%1,%2,%3};"
        : "+f"(c[0]), "+f"(c[1]), "+f"(c[2]), "+f"(c[3])
        : "r"(a[0]), "r"(a[1]), "r"(a[2]), "r"(a[3]), "r"(b0), "r"(b1));
}
__device__ __forceinline__ void mma_tf32(float* c, const uint32_t* a,
                                         uint32_t b0, uint32_t b1) {
    asm volatile(
        "mma.sync.aligned.m16n8k8.row.col.f32.tf32.tf32.f32 "
        "{%0,%1,%2,%3},{%4,%5,%6,%7},{%8,%9},{%0,%1,%2,%3};"
        : "+f"(c[0]), "+f"(c[1]), "+f"(c[2]), "+f"(c[3])
        : "r"(a[0]), "r"(a[1]), "r"(a[2]), "r"(a[3]), "r"(b0), "r"(b1));
}
__device__ __forceinline__ uint32_t sw128(uint32_t o) { return o ^ ((o >> 3) & 0x70); }
__device__ __forceinline__ uint32_t sw64(uint32_t o)  { return o ^ ((o >> 3) & 0x30); }
__device__ __forceinline__ uint32_t f2tf32(float v) {
    uint32_t r;
    asm("cvt.rna.tf32.f32 %0, %1;" : "=r"(r) : "f"(v));
    return r;
}

// Split a float pair into packed bf16x2 hi + packed bf16x2 lo (6 ops total).
__device__ __forceinline__ uint32_t pack_split(float v0, float v1, uint32_t& lp) {
    uint32_t hp;
    asm("cvt.rn.bf16x2.f32 %0, %1, %2;" : "=r"(hp) : "f"(v1), "f"(v0));
    float h0 = __uint_as_float(hp << 16);
    float h1 = __uint_as_float(hp & 0xffff0000u);
    float l0 = v0 - h0, l1 = v1 - h1;
    asm("cvt.rn.bf16x2.f32 %0, %1, %2;" : "=r"(lp) : "f"(l1), "f"(l0));
    return hp;
}
// Hi-only packed convert (1 op).
__device__ __forceinline__ uint32_t pack_hi(float v0, float v1) {
    uint32_t hp;
    asm("cvt.rn.bf16x2.f32 %0, %1, %2;" : "=r"(hp) : "f"(v1), "f"(v0));
    return hp;
}

#define LOG2E 1.4426950408889634f

// ============================ mma.sync bf16 GEMM (QKV only) ============================
#define GBK 32
#define GNCHUNK (D_MODEL / GBK) /* 32 */
#define GARR 8192
#define GST (4 * GARR)
#define GEMM_SMEM (3 * GST)     /* 98304 */

__global__ __launch_bounds__(256, 2) void gemm_mma(
    const bf16* __restrict__ Ah, const bf16* __restrict__ Al,
    const bf16* __restrict__ BhAll, const bf16* __restrict__ BlAll,
    bf16* __restrict__ ChAll, bf16* __restrict__ ClAll, float scale0)
{
    extern __shared__ char smem[];
    const uint32_t sb = smem_u32(smem);
    const int tid = threadIdx.x;
    const int wid = tid >> 5, lane = tid & 31;
    const int wm = wid & 3, wn = wid >> 2;
    const int rowBase = blockIdx.y * 128;
    const int colBase = blockIdx.x * 128;

    const bf16* Bh = BhAll + (size_t)blockIdx.z * WSZ;
    const bf16* Bl = BlAll + (size_t)blockIdx.z * WSZ;

    const bf16* srcAh = Ah + (size_t)rowBase * D_MODEL;
    const bf16* srcAl = Al + (size_t)rowBase * D_MODEL;
    const bf16* srcBh = Bh + (size_t)colBase * D_MODEL;
    const bf16* srcBl = Bl + (size_t)colBase * D_MODEL;

    float acc[2][8][4];
#pragma unroll
    for (int mi = 0; mi < 2; mi++)
#pragma unroll
        for (int ni = 0; ni < 8; ni++)
#pragma unroll
            for (int j = 0; j < 4; j++) acc[mi][ni][j] = 0.f;

    auto load_chunk = [&](int c, int stg) {
        const uint32_t tb = sb + stg * GST;
        const int kofs = c * GBK;
#pragma unroll
        for (int i = 0; i < 2; i++) {
            int f = i * 256 + tid;
            int row = f >> 2, cc = f & 3;
            uint32_t so = sw64((uint32_t)(row * 64 + cc * 16));
            const size_t go = (size_t)row * D_MODEL + kofs + cc * 8;
            cp16(tb + so, srcAh + go);
            cp16(tb + GARR + so, srcAl + go);
            cp16(tb + 2 * GARR + so, srcBh + go);
            cp16(tb + 3 * GARR + so, srcBl + go);
        }
    };

    const uint32_t lrow = lane & 15, lcol = lane >> 4;

    load_chunk(0, 0); cp_commit();
    load_chunk(1, 1); cp_commit();

    for (int c = 0; c < GNCHUNK; c++) {
        if (c + 1 < GNCHUNK) cp_wait<1>(); else cp_wait<0>();
        __syncthreads();
        if (c + 2 < GNCHUNK) { load_chunk(c + 2, (c + 2) % 3); cp_commit(); }

        const uint32_t tb = sb + (c % 3) * GST;
#pragma unroll
        for (int k16 = 0; k16 < 2; k16++) {
            const uint32_t kb = k16 * 32;
            uint32_t a_h[2][4], a_l[2][4], bfr[4][4];
#pragma unroll
            for (int mi = 0; mi < 2; mi++) {
                uint32_t o = (uint32_t)((wm * 32 + mi * 16 + lrow) * 64 + kb + lcol * 16);
                ldsm4(a_h[mi], tb + sw64(o));
                ldsm4(a_l[mi], tb + GARR + sw64(o));
            }
#pragma unroll
            for (int nb = 0; nb < 4; nb++) {
                uint32_t o = (uint32_t)((wn * 64 + nb * 16 + lrow) * 64 + kb + lcol * 16);
                ldsm4(bfr[nb], tb + 2 * GARR + sw64(o));
            }
#pragma unroll
            for (int nb = 0; nb < 4; nb++)
#pragma unroll
                for (int mi = 0; mi < 2; mi++) {
                    mma16816(acc[mi][2 * nb], a_h[mi], bfr[nb][0], bfr[nb][2]);
                    mma16816(acc[mi][2 * nb + 1], a_h[mi], bfr[nb][1], bfr[nb][3]);
                }
#pragma unroll
            for (int nb = 0; nb < 4; nb++)
#pragma unroll
                for (int mi = 0; mi < 2; mi++) {
                    mma16816(acc[mi][2 * nb], a_l[mi], bfr[nb][0], bfr[nb][2]);
                    mma16816(acc[mi][2 * nb + 1], a_l[mi], bfr[nb][1], bfr[nb][3]);
                }
#pragma unroll
            for (int nb = 0; nb < 4; nb++) {
                uint32_t o = (uint32_t)((wn * 64 + nb * 16 + lrow) * 64 + kb + lcol * 16);
                ldsm4(bfr[nb], tb + 3 * GARR + sw64(o));
            }
#pragma unroll
            for (int nb = 0; nb < 4; nb++)
#pragma unroll
                for (int mi = 0; mi < 2; mi++) {
                    mma16816(acc[mi][2 * nb], a_h[mi], bfr[nb][0], bfr[nb][2]);
                    mma16816(acc[mi][2 * nb + 1], a_h[mi], bfr[nb][1], bfr[nb][3]);
                }
        }
    }

    __syncthreads();

    const int g = lane >> 2, t4 = lane & 3;
    bf16* Ch = ChAll + (size_t)blockIdx.z * MTOT * D_MODEL;
    bf16* Cl = ClAll + (size_t)blockIdx.z * MTOT * D_MODEL;
    const float sc = (blockIdx.z == 0) ? scale0 : 1.0f;
#pragma unroll
    for (int mi = 0; mi < 2; mi++)
#pragma unroll
        for (int ni = 0; ni < 8; ni++) {
            int r = rowBase + wm * 32 + mi * 16 + g;
            int col = colBase + wn * 64 + ni * 8 + t4 * 2;
#pragma unroll
            for (int half = 0; half < 2; half++) {
                uint32_t lp;
                uint32_t hp = pack_split(acc[mi][ni][2 * half] * sc,
                                         acc[mi][ni][2 * half + 1] * sc, lp);
                size_t o = (size_t)(r + 8 * half) * D_MODEL + col;
                *(uint32_t*)&Ch[o] = hp;
                *(uint32_t*)&Cl[o] = lp;
            }
        }
}

// ============================ tf32 GEMM (out-projection) ============================
// C[M,1024] = M[M,1024] @ Wt^T; single-pass tf32 (inputs pre-rounded rna).
// Tile 128x128, BK=32 floats, 8 warps (4m x 2n), warp 32x64.
// smem rows padded to 36 floats (144B) -> conflict-free scalar LDS.
#define TROW 36
#define TARR (128 * TROW * 4)    /* 18432 */
#define TST (2 * TARR)           /* 36864 */
#define TSMEM (3 * TST)          /* 110592 */

__global__ __launch_bounds__(256, 2) void gemm_tf32(
    const float* __restrict__ A, const float* __restrict__ Bt,
    float* __restrict__ C)
{
    extern __shared__ char smem[];
    const int tid = threadIdx.x;
    const int wid = tid >> 5, lane = tid & 31;
    const int wm = wid & 3, wn = wid >> 2;
    const int g = lane >> 2, t4 = lane & 3;
    const int rowBase = blockIdx.y * 128;
    const int colBase = blockIdx.x * 128;

    const float* srcA = A + (size_t)rowBase * D_MODEL;
    const float* srcB = Bt + (size_t)colBase * D_MODEL;

    float acc[2][8][4];
#pragma unroll
    for (int mi = 0; mi < 2; mi++)
#pragma unroll
        for (int nb = 0; nb < 8; nb++)
#pragma unroll
            for (int j = 0; j < 4; j++) acc[mi][nb][j] = 0.f;

    const uint32_t sbu = smem_u32(smem);
    auto load_chunk = [&](int c, int stg) {
        const uint32_t tb = sbu + stg * TST;
        const int kofs = c * GBK;
#pragma unroll
        for (int i = 0; i < 4; i++) {
            int f = i * 256 + tid;          // 0..1023
            int row = f >> 3, cc = f & 7;   // 8 cp16 per row (32 floats)
            uint32_t so = (uint32_t)(row * TROW * 4 + cc * 16);
            cp16(tb + so, srcA + (size_t)row * D_MODEL + kofs + cc * 4);
            cp16(tb + TARR + so, srcB + (size_t)row * D_MODEL + kofs + cc * 4);
        }
    };

    load_chunk(0, 0); cp_commit();
    load_chunk(1, 1); cp_commit();

    for (int c = 0; c < GNCHUNK; c++) {
        if (c + 1 < GNCHUNK) cp_wait<1>(); else cp_wait<0>();
        __syncthreads();
        if (c + 2 < GNCHUNK) { load_chunk(c + 2, (c + 2) % 3); cp_commit(); }

        const float* As = (const float*)(smem + (c % 3) * TST);
        const float* Bs = (const float*)(smem + (c % 3) * TST + TARR);
#pragma unroll
        for (int k8 = 0; k8 < 4; k8++) {
            const int kc = k8 * 8 + t4;
            uint32_t a[2][4];
#pragma unroll
            for (int mi = 0; mi < 2; mi++) {
                int r0 = wm * 32 + mi * 16 + g;
                a[mi][0] = __float_as_uint(As[r0 * TROW + kc]);
                a[mi][1] = __float_as_uint(As[(r0 + 8) * TROW + kc]);
                a[mi][2] = __float_as_uint(As[r0 * TROW + kc + 4]);
                a[mi][3] = __float_as_uint(As[(r0 + 8) * TROW + kc + 4]);
            }
#pragma unroll
            for (int nb = 0; nb < 8; nb++) {
                int n = wn * 64 + nb * 8 + g;
                uint32_t b0 = __float_as_uint(Bs[n * TROW + kc]);
                uint32_t b1 = __float_as_uint(Bs[n * TROW + kc + 4]);
#pragma unroll
                for (int mi = 0; mi < 2; mi++)
                    mma_tf32(acc[mi][nb], a[mi], b0, b1);
            }
        }
    }

    __syncthreads();
#pragma unroll
    for (int mi = 0; mi < 2; mi++)
#pragma unroll
        for (int nb = 0; nb < 8; nb++) {
            int r = rowBase + wm * 32 + mi * 16 + g;
            int col = colBase + wn * 64 + nb * 8 + t4 * 2;
            *(float2*)&C[(size_t)r * D_MODEL + col] =
                make_float2(acc[mi][nb][0], acc[mi][nb][1]);
            *(float2*)&C[(size_t)(r + 8) * D_MODEL + col] =
                make_float2(acc[mi][nb][2], acc[mi][nb][3]);
        }
}

// ==================== conversion kernels ====================
__global__ __launch_bounds__(256) void split_kernel(
    const float* __restrict__ in, bf16* __restrict__ hi, bf16* __restrict__ lo, int n2)
{
    int i = blockIdx.x * blockDim.x + threadIdx.x;
    if (i >= n2) return;
    float2 v = ((const float2*)in)[i];
    uint32_t lp;
    uint32_t hp = pack_split(v.x, v.y, lp);
    ((uint32_t*)hi)[i] = hp;
    ((uint32_t*)lo)[i] = lp;
}

__global__ __launch_bounds__(256) void wT_split3(
    const float* __restrict__ W0, const float* __restrict__ W1,
    const float* __restrict__ W2, bf16* __restrict__ Th, bf16* __restrict__ Tl)
{
    const float* W = (blockIdx.z == 0) ? W0 : (blockIdx.z == 1) ? W1 : W2;
    Th += (size_t)blockIdx.z * WSZ;
    Tl += (size_t)blockIdx.z * WSZ;
    __shared__ float t[32][33];
    int nx = blockIdx.x * 32 + threadIdx.x;
#pragma unroll
    for (int j = 0; j < 32; j += 8)
        t[threadIdx.y + j][threadIdx.x] =
            W[(size_t)(blockIdx.y * 32 + threadIdx.y + j) * D_MODEL + nx];
    __syncthreads();
    int k = blockIdx.y * 32 + threadIdx.x;
#pragma unroll
    for (int j = 0; j < 32; j += 8) {
        int n = blockIdx.x * 32 + threadIdx.y + j;
        float v = t[threadIdx.x][threadIdx.y + j];
        bf16 h = __float2bfloat16(v);
        bf16 l = __float2bfloat16(v - __bfloat162float(h));
        Th[(size_t)n * D_MODEL + k] = h;
        Tl[(size_t)n * D_MODEL + k] = l;
    }
}

// fc_o [K][N] fp32 -> Wt [N][K] fp32 (transpose + tf32 rna rounding)
__global__ __launch_bounds__(256) void wT_tf32(
    const float* __restrict__ W, float* __restrict__ T)
{
    __shared__ float t[32][33];
    int nx = blockIdx.x * 32 + threadIdx.x;
#pragma unroll
    for (int j = 0; j < 32; j += 8)
        t[threadIdx.y + j][threadIdx.x] =
            W[(size_t)(blockIdx.y * 32 + threadIdx.y + j) * D_MODEL + nx];
    __syncthreads();
    int k = blockIdx.y * 32 + threadIdx.x;
#pragma unroll
    for (int j = 0; j < 32; j += 8) {
        int n = blockIdx.x * 32 + threadIdx.y + j;
        T[(size_t)n * D_MODEL + k] = __uint_as_float(f2tf32(t[threadIdx.x][threadIdx.y + j]));
    }
}

// ==================== tensor-core flash attention v9' ====================
// R14 best (32 q/warp, double-buffered KV, 2-term PV) with fp32 tf32-rounded
// M output (no bf16 hi/lo split, no ML array).
#define KROW 128
#define AKT 8192
#define ASTG (4 * AKT)
#define AQL (2 * AKT)
#define ATTN_SMEM (2 * ASTG + AQL)     /* 81920 */

__global__ __launch_bounds__(128, 2) void attn_mma(
    const bf16* __restrict__ qkvh, const bf16* __restrict__ qkvl,
    float* __restrict__ Mf)
{
    extern __shared__ char smraw[];
    const uint32_t sb = smem_u32(smraw);
    const int tid = threadIdx.x;
    const int wid = tid >> 5, lane = tid & 31;
    const uint32_t lrow = lane & 15, lcol = lane >> 4;
    const int g = lane >> 2, t4 = lane & 3;

    const int q0 = blockIdx.x * 128;
    const int b = blockIdx.z;
    const size_t qrow = (size_t)b * SEQ + q0;
    const size_t krow0 = (size_t)b * SEQ;
    const int hofs = blockIdx.y * HEAD_DIM;

    auto load_tile = [&](int t, int buf) {
        const size_t kr = krow0 + (size_t)t * 64;
        const uint32_t tb = sb + buf * ASTG;
#pragma unroll
        for (int i = 0; i < 16; i++) {
            int f = i * 128 + tid;
            int arr = f >> 9;
            int r = (f >> 3) & 63, cg = f & 7;
            const bf16* p = ((arr & 1) ? qkvl : qkvh) + ((arr < 2) ? PL : 2 * PL);
            cp16(tb + arr * AKT + sw128((uint32_t)(r * KROW + cg * 16)),
                 p + (kr + r) * D_MODEL + hofs + cg * 8);
        }
    };

#pragma unroll
    for (int i = 0; i < 8; i++) {
        int f = i * 128 + tid;
        int r = f >> 3, cg = f & 7;
        cp16(sb + 2 * ASTG + sw128((uint32_t)(r * KROW + cg * 16)),
             qkvl + (qrow + r) * D_MODEL + hofs + cg * 8);
    }
    load_tile(0, 0); cp_commit();
    load_tile(1, 1); cp_commit();

    uint32_t qhf[2][4][4];
#pragma unroll
    for (int rg = 0; rg < 2; rg++) {
        const size_t r0 = qrow + wid * 32 + rg * 16 + g;
        const int c0 = hofs + t4 * 2;
#pragma unroll
        for (int kc = 0; kc < 4; kc++)
#pragma unroll
            for (int q = 0; q < 4; q++) {
                size_t r = r0 + ((q & 1) ? 8 : 0);
                int c = c0 + kc * 16 + ((q & 2) ? 8 : 0);
                qhf[rg][kc][q] = *(const uint32_t*)&qkvh[r * D_MODEL + c];
            }
    }

    float o[2][8][4];
#pragma unroll
    for (int rg = 0; rg < 2; rg++)
#pragma unroll
        for (int di = 0; di < 8; di++)
#pragma unroll
            for (int j = 0; j < 4; j++) o[rg][di][j] = 0.f;
    float m_prev[2][2] = {{-1e30f, -1e30f}, {-1e30f, -1e30f}};
    float lsum[2][2] = {{0.f, 0.f}, {0.f, 0.f}};

    const int NT = SEQ / 64;
    for (int t = 0; t < NT; t++) {
        if (t + 2 < NT) cp_wait<1>(); else cp_wait<0>();
        __syncthreads();

        const uint32_t tb = sb + (t & 1) * ASTG;

        float s[2][8][4];
#pragma unroll
        for (int rg = 0; rg < 2; rg++)
#pragma unroll
            for (int ni = 0; ni < 8; ni++)
#pragma unroll
                for (int j = 0; j < 4; j++) s[rg][ni][j] = 0.f;

#pragma unroll
        for (int kc = 0; kc < 4; kc++) {
            uint32_t kf[4][4];
#pragma unroll
            for (int np = 0; np < 4; np++)
                ldsm4(kf[np], tb + sw128((uint32_t)((np * 16 + lrow) * KROW +
                                                    kc * 32 + lcol * 16)));
#pragma unroll
            for (int rg = 0; rg < 2; rg++)
#pragma unroll
                for (int ni = 0; ni < 8; ni++) {
                    int np = ni >> 1, hl = ni & 1;
                    mma16816(s[rg][ni], qhf[rg][kc], kf[np][hl], kf[np][hl + 2]);
                }
#pragma unroll
            for (int rg = 0; rg < 2; rg++) {
                uint32_t qlf[4];
                ldsm4(qlf, sb + 2 * ASTG +
                      sw128((uint32_t)((wid * 32 + rg * 16 + lrow) * KROW +
                                       kc * 32 + lcol * 16)));
#pragma unroll
                for (int ni = 0; ni < 8; ni++) {
                    int np = ni >> 1, hl = ni & 1;
                    mma16816(s[rg][ni], qlf, kf[np][hl], kf[np][hl + 2]);
                }
            }
        }
#pragma unroll
        for (int kc = 0; kc < 4; kc++) {
            uint32_t kf[4][4];
#pragma unroll
            for (int np = 0; np < 4; np++)
                ldsm4(kf[np], tb + AKT + sw128((uint32_t)((np * 16 + lrow) * KROW +
                                                          kc * 32 + lcol * 16)));
#pragma unroll
            for (int rg = 0; rg < 2; rg++)
#pragma unroll
                for (int ni = 0; ni < 8; ni++) {
                    int np = ni >> 1, hl = ni & 1;
                    mma16816(s[rg][ni], qhf[rg][kc], kf[np][hl], kf[np][hl + 2]);
                }
        }

#pragma unroll
        for (int rg = 0; rg < 2; rg++)
#pragma unroll
            for (int sub = 0; sub < 2; sub++) {
                float mx = -1e30f;
#pragma unroll
                for (int ni = 0; ni < 8; ni++)
                    mx = fmaxf(mx, fmaxf(s[rg][ni][2 * sub], s[rg][ni][2 * sub + 1]));
                mx = fmaxf(mx, __shfl_xor_sync(0xffffffffu, mx, 1));
                mx = fmaxf(mx, __shfl_xor_sync(0xffffffffu, mx, 2));
                float mn = fmaxf(m_prev[rg][sub], mx);
                float mn2 = mn * LOG2E;
                float al = exp2f(fmaf(m_prev[rg][sub], LOG2E, -mn2));
                float sum = 0.f;
#pragma unroll
                for (int ni = 0; ni < 8; ni++) {
                    float p0 = exp2f(fmaf(s[rg][ni][2 * sub], LOG2E, -mn2));
                    float p1 = exp2f(fmaf(s[rg][ni][2 * sub + 1], LOG2E, -mn2));
                    s[rg][ni][2 * sub] = p0;
                    s[rg][ni][2 * sub + 1] = p1;
                    sum += p0 + p1;
                }
                sum += __shfl_xor_sync(0xffffffffu, sum, 1);
                sum += __shfl_xor_sync(0xffffffffu, sum, 2);
                lsum[rg][sub] = lsum[rg][sub] * al + sum;
                m_prev[rg][sub] = mn;
#pragma unroll
                for (int di = 0; di < 8; di++) {
                    o[rg][di][2 * sub] *= al;
                    o[rg][di][2 * sub + 1] *= al;
                }
            }

#pragma unroll
        for (int kc2 = 0; kc2 < 4; kc2++) {
            int j0 = 2 * kc2, j1 = j0 + 1;
            uint32_t ah[2][4];
#pragma unroll
            for (int rg = 0; rg < 2; rg++)
#pragma unroll
                for (int q = 0; q < 4; q++) {
                    const float* sp = (q & 2) ? s[rg][j1] : s[rg][j0];
                    ah[rg][q] = pack_hi(sp[(q & 1) * 2], sp[(q & 1) * 2 + 1]);
                }
#pragma unroll
            for (int dp = 0; dp < 4; dp++) {
                uint32_t a = sw128((uint32_t)((kc2 * 16 + lrow) * KROW +
                                              dp * 32 + lcol * 16));
                uint32_t vh4[4], vl4[4];
                ldsm4t(vh4, tb + 2 * AKT + a);
                ldsm4t(vl4, tb + 3 * AKT + a);
#pragma unroll
                for (int rg = 0; rg < 2; rg++)
#pragma unroll
                    for (int dd = 0; dd < 2; dd++) {
                        int di = 2 * dp + dd, off = dd * 2;
                        mma16816(o[rg][di], ah[rg], vh4[off], vh4[off + 1]);
                        mma16816(o[rg][di], ah[rg], vl4[off], vl4[off + 1]);
                    }
            }
        }

        __syncthreads();
        if (t + 2 < NT) { load_tile(t + 2, t & 1); cp_commit(); }
    }

    // ---- epilogue: fp32 M, tf32-rounded (feeds tf32 out-proj) ----
#pragma unroll
    for (int rg = 0; rg < 2; rg++) {
        float inv_l[2] = {1.f / lsum[rg][0], 1.f / lsum[rg][1]};
#pragma unroll
        for (int di = 0; di < 8; di++) {
#pragma unroll
            for (int sub = 0; sub < 2; sub++) {
                float v0 = o[rg][di][2 * sub] * inv_l[sub];
                float v1 = o[rg][di][2 * sub + 1] * inv_l[sub];
                size_t idx = (qrow + wid * 32 + rg * 16 + g + 8 * sub) * D_MODEL +
                             hofs + di * 8 + t4 * 2;
                *(float2*)&Mf[idx] = make_float2(__uint_as_float(f2tf32(v0)),
                                                 __uint_as_float(f2tf32(v1)));
            }
        }
    }
}

// ---------------------------------------------------------------------------
extern "C" void kernel_launch(void* const* d_in, const int* in_sizes, int n_in,
                              void* d_out, int out_size)
{
    (void)in_sizes; (void)n_in; (void)out_size;
    const float* x    = (const float*)d_in[0];
    const float* W_q  = (const float*)d_in[1];
    const float* W_k  = (const float*)d_in[2];
    const float* W_v  = (const float*)d_in[3];
    const float* fc_o = (const float*)d_in[4];
    float* out = (float*)d_out;

    bf16 *xh, *xl, *qkvh, *qkvl, *wh, *wl;
    float *mf, *wt;
    cudaGetSymbolAddress((void**)&xh, g_xh);
    cudaGetSymbolAddress((void**)&xl, g_xl);
    cudaGetSymbolAddress((void**)&qkvh, g_qkvh);
    cudaGetSymbolAddress((void**)&qkvl, g_qkvl);
    cudaGetSymbolAddress((void**)&mf, g_m);
    cudaGetSymbolAddress((void**)&wt, g_wt);
    cudaGetSymbolAddress((void**)&wh, g_wh);
    cudaGetSymbolAddress((void**)&wl, g_wl);

    cudaFuncSetAttribute(gemm_mma, cudaFuncAttributeMaxDynamicSharedMemorySize, GEMM_SMEM);
    cudaFuncSetAttribute(gemm_tf32, cudaFuncAttributeMaxDynamicSharedMemorySize, TSMEM);
    cudaFuncSetAttribute(attn_mma, cudaFuncAttributeMaxDynamicSharedMemorySize, ATTN_SMEM);

    const int n2_x = MTOT * D_MODEL / 2;
    dim3 wgrid(D_MODEL / 32, D_MODEL / 32, 3);
    dim3 wgrid1(D_MODEL / 32, D_MODEL / 32, 1);
    dim3 wblk(32, 8);

    split_kernel<<<(n2_x + 255) / 256, 256>>>(x, xh, xl, n2_x);
    wT_split3<<<wgrid, wblk>>>(W_q, W_k, W_v, wh, wl);
    wT_tf32<<<wgrid1, wblk>>>(fc_o, wt);

    dim3 ggrid3(D_MODEL / 128, MTOT / 128, 3);
    gemm_mma<<<ggrid3, 256, GEMM_SMEM>>>(xh, xl, wh, wl, qkvh, qkvl, 0.125f);

    dim3 attn_grid(SEQ / 128, HEADS, BATCH);
    attn_mma<<<attn_grid, 128, ATTN_SMEM>>>(qkvh, qkvl, mf);

    dim3 tgrid(D_MODEL / 128, MTOT / 128);
    gemm_tf32<<<tgrid, 256, TSMEM>>>(mf, wt, out);
}